// round 4
// baseline (speedup 1.0000x reference)
#include <cuda_runtime.h>
#include <cuda_bf16.h>
#include <cstdint>

// Problem constants
#define NROWS 131072
#define KMU   256
#define DDIM  128
#define MT    256                 // rows per CTA tile
#define NTILES (NROWS / MT)       // 512
#define NCTAS  148
#define THREADS 256

// padded smem row: 128 bf16 + 8 pad = 136 elems = 272 bytes (conflict-free ldmatrix)
#define RSTRIDE 272

// dynamic smem byte offsets
#define SA    0                       // x tile: 256 x 272 = 69632
#define SB    69632                   // W tile: 256 x 272 = 69632
#define SADJ  139264                  // 256 floats
#define SXSQ  140288                  // 256 floats
#define SRED  141312                  // 8 floats
#define SMEM_TOTAL 141376

#define L2E 1.4426950408889634f
#define LN2 0.69314718055994531f

__device__ float g_partials[NCTAS];

__device__ __forceinline__ uint32_t smem_u32(const void* p) {
    uint32_t a;
    asm("{ .reg .u64 t; cvta.to.shared.u64 t, %1; cvt.u32.u64 %0, t; }" : "=r"(a) : "l"(p));
    return a;
}

__device__ __forceinline__ void ldm_x4(uint32_t addr, uint32_t& r0, uint32_t& r1,
                                       uint32_t& r2, uint32_t& r3) {
    asm volatile("ldmatrix.sync.aligned.m8n8.x4.shared.b16 {%0,%1,%2,%3}, [%4];"
                 : "=r"(r0), "=r"(r1), "=r"(r2), "=r"(r3) : "r"(addr));
}

__device__ __forceinline__ void mma16816(float* d, const uint32_t* a, const uint32_t* b) {
    asm volatile(
        "mma.sync.aligned.m16n8k16.row.col.f32.bf16.bf16.f32 "
        "{%0,%1,%2,%3}, {%4,%5,%6,%7}, {%8,%9}, {%0,%1,%2,%3};"
        : "+f"(d[0]), "+f"(d[1]), "+f"(d[2]), "+f"(d[3])
        : "r"(a[0]), "r"(a[1]), "r"(a[2]), "r"(a[3]), "r"(b[0]), "r"(b[1]));
}

__device__ __forceinline__ float ex2f(float x) {
    float y; asm("ex2.approx.ftz.f32 %0, %1;" : "=f"(y) : "f"(x)); return y;
}
__device__ __forceinline__ float lg2f(float x) {
    float y; asm("lg2.approx.ftz.f32 %0, %1;" : "=f"(y) : "f"(x)); return y;
}

__global__ void __launch_bounds__(THREADS)
gmm_lse_kernel(const float* __restrict__ x, const float* __restrict__ mu,
               const float* __restrict__ prec) {
    extern __shared__ char smem[];
    const uint32_t sb = smem_u32(smem);
    const int tid = threadIdx.x;
    const int w = tid >> 5;
    const int l = tid & 31;

    float* adj_s = (float*)(smem + SADJ);
    float* xsq_s = (float*)(smem + SXSQ);
    float* red_s = (float*)(smem + SRED);

    // per-lane precision slice (cols 4l..4l+3) — reused for both W and x staging
    const float4 pc = ((const float4*)prec)[l];

    // ---- stage W = prec*mu as bf16 (once per CTA), adj[k] = -0.5*mu_sq[k]*log2e ----
    {
        const float4* mr = (const float4*)(mu + (long)(w * 32) * DDIM);
        #pragma unroll 4
        for (int i = 0; i < 32; i++) {
            const int krow = w * 32 + i;
            float4 f = mr[i * 32 + l];
            float wx = pc.x * f.x, wy = pc.y * f.y, wz = pc.z * f.z, ww = pc.w * f.w;
            float s = wx * f.x;
            s = fmaf(wy, f.y, s);
            s = fmaf(wz, f.z, s);
            s = fmaf(ww, f.w, s);
            #pragma unroll
            for (int o = 16; o; o >>= 1) s += __shfl_xor_sync(0xFFFFFFFFu, s, o);
            __nv_bfloat162 lo = __floats2bfloat162_rn(wx, wy);
            __nv_bfloat162 hi = __floats2bfloat162_rn(wz, ww);
            uint2 v;
            v.x = *(uint32_t*)&lo;
            v.y = *(uint32_t*)&hi;
            *(uint2*)(smem + SB + krow * RSTRIDE + l * 8) = v;
            if (l == 0) adj_s[krow] = -0.5f * s * L2E;
        }
    }

    float acc_thr = 0.f;

    for (int tile = blockIdx.x; tile < NTILES; tile += gridDim.x) {
        // ---- stage x tile (coalesced): warp w loads rows w*32..w*32+31 ----
        const float4* xr = (const float4*)(x + (long)(tile * MT + w * 32) * DDIM);
        #pragma unroll 4
        for (int i = 0; i < 32; i++) {
            float4 f = xr[i * 32 + l];
            float s = pc.x * f.x * f.x;
            s = fmaf(pc.y * f.y, f.y, s);
            s = fmaf(pc.z * f.z, f.z, s);
            s = fmaf(pc.w * f.w, f.w, s);
            #pragma unroll
            for (int o = 16; o; o >>= 1) s += __shfl_xor_sync(0xFFFFFFFFu, s, o);
            __nv_bfloat162 lo = __floats2bfloat162_rn(f.x, f.y);
            __nv_bfloat162 hi = __floats2bfloat162_rn(f.z, f.w);
            uint2 v;
            v.x = *(uint32_t*)&lo;
            v.y = *(uint32_t*)&hi;
            *(uint2*)(smem + SA + (w * 32 + i) * RSTRIDE + l * 8) = v;
            if (l == 0) xsq_s[w * 32 + i] = s;
        }
        __syncthreads();

        // ---- GEMM + fused logsumexp; warp w owns rows w*32..w*32+31 ----
        const int mb = w * 32;
        const int m = l >> 3, r = l & 7;
        float run_m[4], run_s[4];
        #pragma unroll
        for (int ri = 0; ri < 4; ri++) { run_m[ri] = -1e30f; run_s[ri] = 0.f; }

        #pragma unroll 1
        for (int c = 0; c < 4; c++) {
            // adj values for this lane's columns (reused across mt/sub)
            float av[16];
            #pragma unroll
            for (int t = 0; t < 8; t++) {
                const int col = c * 64 + 8 * t + 2 * (l & 3);
                av[2 * t]     = adj_s[col];
                av[2 * t + 1] = adj_s[col + 1];
            }

            float acc[2][8][4] = {};
            #pragma unroll
            for (int ks = 0; ks < 8; ks++) {
                uint32_t a[2][4];
                #pragma unroll
                for (int mt = 0; mt < 2; mt++) {
                    uint32_t addr = sb + SA
                        + (mb + mt * 16 + ((m & 1) << 3) + r) * RSTRIDE
                        + ((ks << 4) + ((m >> 1) << 3)) * 2;
                    ldm_x4(addr, a[mt][0], a[mt][1], a[mt][2], a[mt][3]);
                }
                uint32_t b[4][4];
                #pragma unroll
                for (int tp = 0; tp < 4; tp++) {
                    uint32_t addr = sb + SB
                        + (c * 64 + tp * 16 + ((m >> 1) << 3) + r) * RSTRIDE
                        + ((ks << 4) + ((m & 1) << 3)) * 2;
                    ldm_x4(addr, b[tp][0], b[tp][1], b[tp][2], b[tp][3]);
                }
                #pragma unroll
                for (int mt = 0; mt < 2; mt++)
                    #pragma unroll
                    for (int t = 0; t < 8; t++)
                        mma16816(acc[mt][t], a[mt], &b[t >> 1][(t & 1) * 2]);
            }

            // fold this 64-col chunk into running (max,sum) per owned row
            #pragma unroll
            for (int mt = 0; mt < 2; mt++) {
                #pragma unroll
                for (int sub = 0; sub < 2; sub++) {
                    const int ri = mt * 2 + sub;
                    float v[16];
                    #pragma unroll
                    for (int t = 0; t < 8; t++) {
                        v[2 * t]     = fmaf(acc[mt][t][sub * 2],     L2E, av[2 * t]);
                        v[2 * t + 1] = fmaf(acc[mt][t][sub * 2 + 1], L2E, av[2 * t + 1]);
                    }
                    float cm = v[0];
                    #pragma unroll
                    for (int j = 1; j < 16; j++) cm = fmaxf(cm, v[j]);
                    if (cm > run_m[ri]) {
                        run_s[ri] *= ex2f(run_m[ri] - cm);
                        run_m[ri] = cm;
                    }
                    float s = 0.f;
                    #pragma unroll
                    for (int j = 0; j < 16; j++) s += ex2f(v[j] - run_m[ri]);
                    run_s[ri] += s;
                }
            }
        }

        // ---- cross-lane combine within quad (lane%4 spans columns) ----
        #pragma unroll
        for (int ri = 0; ri < 4; ri++) {
            float rm = run_m[ri], rs = run_s[ri];
            #pragma unroll
            for (int o = 1; o <= 2; o <<= 1) {
                float om = __shfl_xor_sync(0xFFFFFFFFu, rm, o);
                float os = __shfl_xor_sync(0xFFFFFFFFu, rs, o);
                float nm = fmaxf(rm, om);
                rs = rs * ex2f(rm - nm) + os * ex2f(om - nm);
                rm = nm;
            }
            if ((l & 3) == 0) {
                const int mt = ri >> 1, sub = ri & 1;
                const int row = mb + mt * 16 + sub * 8 + (l >> 2);
                acc_thr += LN2 * (rm + lg2f(rs)) - 0.5f * xsq_s[row];
            }
        }
        __syncthreads();  // before next tile overwrites SA
    }

    // ---- deterministic block reduction ----
    float a = acc_thr;
    #pragma unroll
    for (int o = 16; o; o >>= 1) a += __shfl_xor_sync(0xFFFFFFFFu, a, o);
    if (l == 0) red_s[w] = a;
    __syncthreads();
    if (tid == 0) {
        float t = 0.f;
        #pragma unroll
        for (int i = 0; i < 8; i++) t += red_s[i];
        g_partials[blockIdx.x] = t;
    }
}

__global__ void reduce_kernel(float* __restrict__ out) {
    __shared__ float s[256];
    const int tid = threadIdx.x;
    float a = 0.f;
    for (int i = tid; i < NCTAS; i += 256) a += g_partials[i];
    s[tid] = a;
    __syncthreads();
    for (int o = 128; o > 0; o >>= 1) {
        if (tid < o) s[tid] += s[tid + o];
        __syncthreads();
    }
    if (tid == 0) out[0] = -s[0];
}

extern "C" void kernel_launch(void* const* d_in, const int* in_sizes, int n_in,
                              void* d_out, int out_size) {
    const float* x    = (const float*)d_in[0];
    const float* mu   = (const float*)d_in[1];
    const float* prec = (const float*)d_in[2];
    float* out = (float*)d_out;

    cudaFuncSetAttribute(gmm_lse_kernel, cudaFuncAttributeMaxDynamicSharedMemorySize, SMEM_TOTAL);
    gmm_lse_kernel<<<NCTAS, THREADS, SMEM_TOTAL>>>(x, mu, prec);
    reduce_kernel<<<1, 256>>>(out);
}

// round 5
// speedup vs baseline: 1.0868x; 1.0868x over previous
#include <cuda_runtime.h>
#include <cuda_bf16.h>
#include <cuda_fp16.h>
#include <cstdint>

// Problem constants
#define NROWS 131072
#define KMU   256
#define DDIM  128
#define MT    256                 // rows per CTA tile
#define NTILES (NROWS / MT)       // 512
#define NCTAS  148
#define THREADS 256

// padded smem row: 128 bf16 + 8 pad = 136 elems = 272 bytes (conflict-free ldmatrix)
#define RSTRIDE 272

// dynamic smem byte offsets
#define SA    0                       // x tile: 256 x 272 = 69632
#define SB    69632                   // W tile: 256 x 272 = 69632
#define SADJ  139264                  // 256 floats
#define SRED  140288                  // 8 floats
#define SMEM_TOTAL 140352

#define L2E 1.4426950408889634f
#define LN2 0.69314718055994531f

__device__ float g_partials[NCTAS];
__device__ unsigned int g_count = 0;

__device__ __forceinline__ uint32_t smem_u32(const void* p) {
    uint32_t a;
    asm("{ .reg .u64 t; cvta.to.shared.u64 t, %1; cvt.u32.u64 %0, t; }" : "=r"(a) : "l"(p));
    return a;
}

__device__ __forceinline__ void ldm_x4(uint32_t addr, uint32_t& r0, uint32_t& r1,
                                       uint32_t& r2, uint32_t& r3) {
    asm volatile("ldmatrix.sync.aligned.m8n8.x4.shared.b16 {%0,%1,%2,%3}, [%4];"
                 : "=r"(r0), "=r"(r1), "=r"(r2), "=r"(r3) : "r"(addr));
}

__device__ __forceinline__ void mma16816(float* d, const uint32_t* a, const uint32_t* b) {
    asm volatile(
        "mma.sync.aligned.m16n8k16.row.col.f32.bf16.bf16.f32 "
        "{%0,%1,%2,%3}, {%4,%5,%6,%7}, {%8,%9}, {%0,%1,%2,%3};"
        : "+f"(d[0]), "+f"(d[1]), "+f"(d[2]), "+f"(d[3])
        : "r"(a[0]), "r"(a[1]), "r"(a[2]), "r"(a[3]), "r"(b[0]), "r"(b[1]));
}

__device__ __forceinline__ float ex2f(float x) {
    float y; asm("ex2.approx.ftz.f32 %0, %1;" : "=f"(y) : "f"(x)); return y;
}
__device__ __forceinline__ float lg2f(float x) {
    float y; asm("lg2.approx.ftz.f32 %0, %1;" : "=f"(y) : "f"(x)); return y;
}

__global__ void __launch_bounds__(THREADS)
gmm_lse_kernel(const float* __restrict__ x, const float* __restrict__ mu,
               const float* __restrict__ prec, float* __restrict__ out) {
    extern __shared__ char smem[];
    const uint32_t sb = smem_u32(smem);
    const int tid = threadIdx.x;
    const int w = tid >> 5;
    const int l = tid & 31;

    float* adj_s = (float*)(smem + SADJ);
    float* red_s = (float*)(smem + SRED);
    __shared__ unsigned int last_flag;

    // per-lane precision slice (cols 4l..4l+3) — reused for both W and x staging
    const float4 pc = ((const float4*)prec)[l];

    // ---- stage W = prec*mu as bf16 (once per CTA), adj[k] = -0.5*mu_sq[k]*log2e ----
    {
        const float4* mr = (const float4*)(mu + (long)(w * 32) * DDIM);
        #pragma unroll 4
        for (int i = 0; i < 32; i++) {
            const int krow = w * 32 + i;
            float4 f = mr[i * 32 + l];
            float wx = pc.x * f.x, wy = pc.y * f.y, wz = pc.z * f.z, ww = pc.w * f.w;
            float s = wx * f.x;
            s = fmaf(wy, f.y, s);
            s = fmaf(wz, f.z, s);
            s = fmaf(ww, f.w, s);
            #pragma unroll
            for (int o = 16; o; o >>= 1) s += __shfl_xor_sync(0xFFFFFFFFu, s, o);
            __nv_bfloat162 lo = __floats2bfloat162_rn(wx, wy);
            __nv_bfloat162 hi = __floats2bfloat162_rn(wz, ww);
            uint2 v;
            v.x = *(uint32_t*)&lo;
            v.y = *(uint32_t*)&hi;
            *(uint2*)(smem + SB + krow * RSTRIDE + l * 8) = v;
            if (l == 0) adj_s[krow] = -0.5f * s * L2E;
        }
    }

    float acc_thr = 0.f;   // sum of LSE' over owned rows
    float xsq_acc = 0.f;   // thread-local sum of prec*x^2 over loaded elements

    for (int tile = blockIdx.x; tile < NTILES; tile += gridDim.x) {
        // ---- stage x tile (coalesced): warp w loads rows w*32..w*32+31 ----
        const float4* xr = (const float4*)(x + (long)(tile * MT + w * 32) * DDIM);
        #pragma unroll 8
        for (int i = 0; i < 32; i++) {
            float4 f = xr[i * 32 + l];
            xsq_acc = fmaf(pc.x * f.x, f.x, xsq_acc);
            xsq_acc = fmaf(pc.y * f.y, f.y, xsq_acc);
            xsq_acc = fmaf(pc.z * f.z, f.z, xsq_acc);
            xsq_acc = fmaf(pc.w * f.w, f.w, xsq_acc);
            __nv_bfloat162 lo = __floats2bfloat162_rn(f.x, f.y);
            __nv_bfloat162 hi = __floats2bfloat162_rn(f.z, f.w);
            uint2 v;
            v.x = *(uint32_t*)&lo;
            v.y = *(uint32_t*)&hi;
            *(uint2*)(smem + SA + (w * 32 + i) * RSTRIDE + l * 8) = v;
        }
        __syncthreads();

        // ---- GEMM + fused logsumexp; warp w owns rows w*32..w*32+31 ----
        const int mb = w * 32;
        const int m = l >> 3, r = l & 7;
        float run_m[4], run_s[4];
        #pragma unroll
        for (int ri = 0; ri < 4; ri++) { run_m[ri] = -1e30f; run_s[ri] = 0.f; }

        #pragma unroll 1
        for (int c = 0; c < 4; c++) {
            // adj values for this lane's columns (reused across mt/sub)
            float av[16];
            #pragma unroll
            for (int t = 0; t < 8; t++) {
                const int col = c * 64 + 8 * t + 2 * (l & 3);
                av[2 * t]     = adj_s[col];
                av[2 * t + 1] = adj_s[col + 1];
            }

            float acc[2][8][4] = {};
            #pragma unroll
            for (int ks = 0; ks < 8; ks++) {
                uint32_t a[2][4];
                #pragma unroll
                for (int mt = 0; mt < 2; mt++) {
                    uint32_t addr = sb + SA
                        + (mb + mt * 16 + ((m & 1) << 3) + r) * RSTRIDE
                        + ((ks << 4) + ((m >> 1) << 3)) * 2;
                    ldm_x4(addr, a[mt][0], a[mt][1], a[mt][2], a[mt][3]);
                }
                uint32_t b[4][4];
                #pragma unroll
                for (int tp = 0; tp < 4; tp++) {
                    uint32_t addr = sb + SB
                        + (c * 64 + tp * 16 + ((m >> 1) << 3) + r) * RSTRIDE
                        + ((ks << 4) + ((m & 1) << 3)) * 2;
                    ldm_x4(addr, b[tp][0], b[tp][1], b[tp][2], b[tp][3]);
                }
                #pragma unroll
                for (int mt = 0; mt < 2; mt++)
                    #pragma unroll
                    for (int t = 0; t < 8; t++)
                        mma16816(acc[mt][t], a[mt], &b[t >> 1][(t & 1) * 2]);
            }

            // fold this 64-col chunk into running (max,sum) per owned row
            #pragma unroll
            for (int mt = 0; mt < 2; mt++) {
                #pragma unroll
                for (int sub = 0; sub < 2; sub++) {
                    const int ri = mt * 2 + sub;
                    float v[16];
                    #pragma unroll
                    for (int t = 0; t < 8; t++) {
                        v[2 * t]     = fmaf(acc[mt][t][sub * 2],     L2E, av[2 * t]);
                        v[2 * t + 1] = fmaf(acc[mt][t][sub * 2 + 1], L2E, av[2 * t + 1]);
                    }
                    float cm = v[0];
                    #pragma unroll
                    for (int j = 1; j < 16; j++) cm = fmaxf(cm, v[j]);
                    if (cm > run_m[ri]) {
                        run_s[ri] *= ex2f(run_m[ri] - cm);
                        run_m[ri] = cm;
                    }
                    const float rm = run_m[ri];
                    // fp16x2 exp: 2 exps per MUFU op, pairwise half2 sum tree
                    __half2 e[8];
                    #pragma unroll
                    for (int t = 0; t < 8; t++)
                        e[t] = h2exp2(__floats2half2_rn(v[2 * t] - rm, v[2 * t + 1] - rm));
                    e[0] = __hadd2(e[0], e[1]);
                    e[2] = __hadd2(e[2], e[3]);
                    e[4] = __hadd2(e[4], e[5]);
                    e[6] = __hadd2(e[6], e[7]);
                    e[0] = __hadd2(e[0], e[2]);
                    e[4] = __hadd2(e[4], e[6]);
                    e[0] = __hadd2(e[0], e[4]);
                    float2 f2 = __half22float2(e[0]);
                    run_s[ri] += f2.x + f2.y;
                }
            }
        }

        // ---- cross-lane combine within quad (lane%4 spans columns) ----
        #pragma unroll
        for (int ri = 0; ri < 4; ri++) {
            float rm = run_m[ri], rs = run_s[ri];
            #pragma unroll
            for (int o = 1; o <= 2; o <<= 1) {
                float om = __shfl_xor_sync(0xFFFFFFFFu, rm, o);
                float os = __shfl_xor_sync(0xFFFFFFFFu, rs, o);
                float nm = fmaxf(rm, om);
                rs = rs * ex2f(rm - nm) + os * ex2f(om - nm);
                rm = nm;
            }
            if ((l & 3) == 0)
                acc_thr += LN2 * (rm + lg2f(rs));
        }
        __syncthreads();  // before next tile overwrites SA
    }

    // fold thread-local xsq into the LSE sum (additive pass-through of logsumexp)
    acc_thr -= 0.5f * xsq_acc;

    // ---- deterministic block reduction ----
    float a = acc_thr;
    #pragma unroll
    for (int o = 16; o; o >>= 1) a += __shfl_xor_sync(0xFFFFFFFFu, a, o);
    if (l == 0) red_s[w] = a;
    __syncthreads();
    if (tid == 0) {
        float t = 0.f;
        #pragma unroll
        for (int i = 0; i < 8; i++) t += red_s[i];
        g_partials[blockIdx.x] = t;
        __threadfence();
        unsigned int c = atomicAdd(&g_count, 1u);
        last_flag = (c == (unsigned)(gridDim.x - 1)) ? 1u : 0u;
    }
    __syncthreads();

    // ---- last CTA: deterministic final reduction (fixed lane->index map) ----
    if (last_flag && w == 0) {
        float s = 0.f;
        #pragma unroll
        for (int i = l; i < NCTAS; i += 32) s += __ldcg(&g_partials[i]);
        #pragma unroll
        for (int o = 16; o; o >>= 1) s += __shfl_xor_sync(0xFFFFFFFFu, s, o);
        if (l == 0) {
            out[0] = -s;
            g_count = 0;          // reset for next graph replay
            __threadfence();
        }
    }
}

extern "C" void kernel_launch(void* const* d_in, const int* in_sizes, int n_in,
                              void* d_out, int out_size) {
    const float* x    = (const float*)d_in[0];
    const float* mu   = (const float*)d_in[1];
    const float* prec = (const float*)d_in[2];
    float* out = (float*)d_out;

    cudaFuncSetAttribute(gmm_lse_kernel, cudaFuncAttributeMaxDynamicSharedMemorySize, SMEM_TOTAL);
    gmm_lse_kernel<<<NCTAS, THREADS, SMEM_TOTAL>>>(x, mu, prec, out);
}

// round 6
// speedup vs baseline: 1.1900x; 1.0950x over previous
#include <cuda_runtime.h>
#include <cuda_bf16.h>
#include <cuda_fp16.h>
#include <cstdint>

// Problem constants
#define NROWS 131072
#define KMU   256
#define DDIM  128
#define MT    128                 // rows per CTA tile
#define NTILES (NROWS / MT)       // 1024
#define NCTAS  296                // 2 per SM
#define THREADS 256

// padded smem row: 128 bf16 + 8 pad = 136 elems = 272 bytes (conflict-free ldmatrix)
#define RSTRIDE 272
#define BUFSZ   (MT * RSTRIDE)    // 34816 per x buffer

// dynamic smem byte offsets
// [0 .. 69632): prologue = W tile (256 x 272); afterwards = 2 x-tile buffers
#define SBUF  0
#define SADJ  69632                   // 256 floats
#define SPM   70656                   // 128 x 9 floats (padded, conflict-free)
#define SPS   75264                   // 128 x 9 floats
#define SRED  79872                   // 8 floats
#define SMEM_TOTAL 79936

#define L2E 1.4426950408889634f
#define LN2 0.69314718055994531f

__device__ float g_partials[NCTAS];
__device__ unsigned int g_count = 0;

__device__ __forceinline__ uint32_t smem_u32(const void* p) {
    uint32_t a;
    asm("{ .reg .u64 t; cvta.to.shared.u64 t, %1; cvt.u32.u64 %0, t; }" : "=r"(a) : "l"(p));
    return a;
}

__device__ __forceinline__ void ldm_x4(uint32_t addr, uint32_t& r0, uint32_t& r1,
                                       uint32_t& r2, uint32_t& r3) {
    asm volatile("ldmatrix.sync.aligned.m8n8.x4.shared.b16 {%0,%1,%2,%3}, [%4];"
                 : "=r"(r0), "=r"(r1), "=r"(r2), "=r"(r3) : "r"(addr));
}

__device__ __forceinline__ void mma16816(float* d, const uint32_t* a, const uint32_t* b) {
    asm volatile(
        "mma.sync.aligned.m16n8k16.row.col.f32.bf16.bf16.f32 "
        "{%0,%1,%2,%3}, {%4,%5,%6,%7}, {%8,%9}, {%0,%1,%2,%3};"
        : "+f"(d[0]), "+f"(d[1]), "+f"(d[2]), "+f"(d[3])
        : "r"(a[0]), "r"(a[1]), "r"(a[2]), "r"(a[3]), "r"(b[0]), "r"(b[1]));
}

__device__ __forceinline__ float ex2f(float x) {
    float y; asm("ex2.approx.ftz.f32 %0, %1;" : "=f"(y) : "f"(x)); return y;
}
__device__ __forceinline__ float lg2f(float x) {
    float y; asm("lg2.approx.ftz.f32 %0, %1;" : "=f"(y) : "f"(x)); return y;
}

__global__ void __launch_bounds__(THREADS, 2)
gmm_lse_kernel(const float* __restrict__ x, const float* __restrict__ mu,
               const float* __restrict__ prec, float* __restrict__ out) {
    extern __shared__ char smem[];
    const uint32_t sb = smem_u32(smem);
    const int tid = threadIdx.x;
    const int w = tid >> 5;
    const int l = tid & 31;
    const int m = l >> 3, r = l & 7;

    float* adj_s = (float*)(smem + SADJ);
    float* pm_s  = (float*)(smem + SPM);
    float* ps_s  = (float*)(smem + SPS);
    float* red_s = (float*)(smem + SRED);
    __shared__ unsigned int last_flag;

    // per-lane precision slice (cols 4l..4l+3)
    const float4 pc = ((const float4*)prec)[l];

    // ---- prologue: stage W = prec*mu as bf16 into [0,69632), adj[k] ----
    {
        const float4* mr = (const float4*)(mu + (long)(w * 32) * DDIM);
        #pragma unroll 4
        for (int i = 0; i < 32; i++) {
            const int krow = w * 32 + i;
            float4 f = mr[i * 32 + l];
            float wx = pc.x * f.x, wy = pc.y * f.y, wz = pc.z * f.z, ww = pc.w * f.w;
            float s = wx * f.x;
            s = fmaf(wy, f.y, s);
            s = fmaf(wz, f.z, s);
            s = fmaf(ww, f.w, s);
            #pragma unroll
            for (int o = 16; o; o >>= 1) s += __shfl_xor_sync(0xFFFFFFFFu, s, o);
            __nv_bfloat162 lo = __floats2bfloat162_rn(wx, wy);
            __nv_bfloat162 hi = __floats2bfloat162_rn(wz, ww);
            uint2 v;
            v.x = *(uint32_t*)&lo;
            v.y = *(uint32_t*)&hi;
            *(uint2*)(smem + SBUF + krow * RSTRIDE + l * 8) = v;
            if (l == 0) adj_s[krow] = -0.5f * s * L2E;
        }
    }
    __syncthreads();

    // ---- load register-resident B fragments: warp w owns clusters w*32..w*32+31 ----
    uint32_t B[8][2][4];
    #pragma unroll
    for (int ks = 0; ks < 8; ks++) {
        #pragma unroll
        for (int tp = 0; tp < 2; tp++) {
            uint32_t addr = sb + SBUF
                + (w * 32 + tp * 16 + ((m >> 1) << 3) + r) * RSTRIDE
                + ((ks << 4) + ((m & 1) << 3)) * 2;
            ldm_x4(addr, B[ks][tp][0], B[ks][tp][1], B[ks][tp][2], B[ks][tp][3]);
        }
    }
    // adj values for this lane's 8 columns (constant across tiles)
    float av[8];
    #pragma unroll
    for (int t = 0; t < 4; t++) {
        const int col = w * 32 + 8 * t + 2 * (l & 3);
        av[2 * t]     = adj_s[col];
        av[2 * t + 1] = adj_s[col + 1];
    }
    __syncthreads();   // done reading W region; becomes x double-buffer

    float acc_thr = 0.f;
    float xsq_acc = 0.f;

    // ---- stage first tile into buf0 ----
    {
        const int tile0 = blockIdx.x;
        const float4* xr = (const float4*)(x + (long)(tile0 * MT + w * 16) * DDIM);
        #pragma unroll 8
        for (int i = 0; i < 16; i++) {
            float4 f = xr[i * 32 + l];
            xsq_acc = fmaf(pc.x * f.x, f.x, xsq_acc);
            xsq_acc = fmaf(pc.y * f.y, f.y, xsq_acc);
            xsq_acc = fmaf(pc.z * f.z, f.z, xsq_acc);
            xsq_acc = fmaf(pc.w * f.w, f.w, xsq_acc);
            __nv_bfloat162 lo = __floats2bfloat162_rn(f.x, f.y);
            __nv_bfloat162 hi = __floats2bfloat162_rn(f.z, f.w);
            uint2 v;
            v.x = *(uint32_t*)&lo;
            v.y = *(uint32_t*)&hi;
            *(uint2*)(smem + SBUF + (w * 16 + i) * RSTRIDE + l * 8) = v;
        }
    }
    __syncthreads();

    int par = 0;
    for (int tile = blockIdx.x; tile < NTILES; tile += gridDim.x, par ^= 1) {
        const uint32_t cur = sb + SBUF + par * BUFSZ;

        // ---- stage NEXT tile into the other buffer (LDGs issue before compute) ----
        const int nxt = tile + gridDim.x;
        if (nxt < NTILES) {
            const float4* xr = (const float4*)(x + (long)(nxt * MT + w * 16) * DDIM);
            #pragma unroll 8
            for (int i = 0; i < 16; i++) {
                float4 f = xr[i * 32 + l];
                xsq_acc = fmaf(pc.x * f.x, f.x, xsq_acc);
                xsq_acc = fmaf(pc.y * f.y, f.y, xsq_acc);
                xsq_acc = fmaf(pc.z * f.z, f.z, xsq_acc);
                xsq_acc = fmaf(pc.w * f.w, f.w, xsq_acc);
                __nv_bfloat162 lo = __floats2bfloat162_rn(f.x, f.y);
                __nv_bfloat162 hi = __floats2bfloat162_rn(f.z, f.w);
                uint2 v;
                v.x = *(uint32_t*)&lo;
                v.y = *(uint32_t*)&hi;
                *(uint2*)(smem + SBUF + (par ^ 1) * BUFSZ + (w * 16 + i) * RSTRIDE + l * 8) = v;
            }
        }

        // ---- compute: warp w = all 128 rows x its 32 clusters ----
        #pragma unroll 1
        for (int mt = 0; mt < 8; mt++) {
            float acc[4][4] = {};
            #pragma unroll
            for (int ks = 0; ks < 8; ks++) {
                uint32_t a[4];
                uint32_t addr = cur
                    + (mt * 16 + ((m & 1) << 3) + r) * RSTRIDE
                    + ((ks << 4) + ((m >> 1) << 3)) * 2;
                ldm_x4(addr, a[0], a[1], a[2], a[3]);
                #pragma unroll
                for (int t = 0; t < 4; t++)
                    mma16816(acc[t], a, &B[ks][t >> 1][(t & 1) * 2]);
            }
            // epilogue: per-row (max,sum) over this warp's 32 cols
            #pragma unroll
            for (int sub = 0; sub < 2; sub++) {
                float v[8];
                #pragma unroll
                for (int t = 0; t < 4; t++) {
                    v[2 * t]     = fmaf(acc[t][sub * 2],     L2E, av[2 * t]);
                    v[2 * t + 1] = fmaf(acc[t][sub * 2 + 1], L2E, av[2 * t + 1]);
                }
                float cm = v[0];
                #pragma unroll
                for (int j = 1; j < 8; j++) cm = fmaxf(cm, v[j]);
                __half2 e0 = h2exp2(__floats2half2_rn(v[0] - cm, v[1] - cm));
                __half2 e1 = h2exp2(__floats2half2_rn(v[2] - cm, v[3] - cm));
                __half2 e2 = h2exp2(__floats2half2_rn(v[4] - cm, v[5] - cm));
                __half2 e3 = h2exp2(__floats2half2_rn(v[6] - cm, v[7] - cm));
                e0 = __hadd2(e0, e1);
                e2 = __hadd2(e2, e3);
                e0 = __hadd2(e0, e2);
                float2 f2 = __half22float2(e0);
                float s = f2.x + f2.y;
                // quad combine (lane%4 spans columns)
                #pragma unroll
                for (int o = 1; o <= 2; o <<= 1) {
                    float om = __shfl_xor_sync(0xFFFFFFFFu, cm, o);
                    float os = __shfl_xor_sync(0xFFFFFFFFu, s, o);
                    float nm = fmaxf(cm, om);
                    s = s * ex2f(cm - nm) + os * ex2f(om - nm);
                    cm = nm;
                }
                if ((l & 3) == 0) {
                    const int row = mt * 16 + sub * 8 + (l >> 2);
                    pm_s[row * 9 + w] = cm;
                    ps_s[row * 9 + w] = s;
                }
            }
        }
        __syncthreads();

        // ---- exact 8-way cross-warp merge; threads 0..127 own one row each ----
        if (tid < MT) {
            float m8 = pm_s[tid * 9];
            #pragma unroll
            for (int j = 1; j < 8; j++) m8 = fmaxf(m8, pm_s[tid * 9 + j]);
            float s8 = 0.f;
            #pragma unroll
            for (int j = 0; j < 8; j++)
                s8 += ps_s[tid * 9 + j] * ex2f(pm_s[tid * 9 + j] - m8);
            acc_thr += LN2 * (m8 + lg2f(s8));
        }
        __syncthreads();
    }

    // fold thread-local xsq (additive pass-through of logsumexp)
    acc_thr -= 0.5f * xsq_acc;

    // ---- deterministic block reduction ----
    float a = acc_thr;
    #pragma unroll
    for (int o = 16; o; o >>= 1) a += __shfl_xor_sync(0xFFFFFFFFu, a, o);
    if (l == 0) red_s[w] = a;
    __syncthreads();
    if (tid == 0) {
        float t = 0.f;
        #pragma unroll
        for (int i = 0; i < 8; i++) t += red_s[i];
        g_partials[blockIdx.x] = t;
        __threadfence();
        unsigned int c = atomicAdd(&g_count, 1u);
        last_flag = (c == (unsigned)(gridDim.x - 1)) ? 1u : 0u;
    }
    __syncthreads();

    // ---- last CTA: deterministic final reduction (fixed lane->index map) ----
    if (last_flag && w == 0) {
        float s = 0.f;
        #pragma unroll
        for (int i = l; i < NCTAS; i += 32) s += __ldcg(&g_partials[i]);
        #pragma unroll
        for (int o = 16; o; o >>= 1) s += __shfl_xor_sync(0xFFFFFFFFu, s, o);
        if (l == 0) {
            out[0] = -s;
            g_count = 0;          // reset for next graph replay
            __threadfence();
        }
    }
}

extern "C" void kernel_launch(void* const* d_in, const int* in_sizes, int n_in,
                              void* d_out, int out_size) {
    const float* x    = (const float*)d_in[0];
    const float* mu   = (const float*)d_in[1];
    const float* prec = (const float*)d_in[2];
    float* out = (float*)d_out;

    cudaFuncSetAttribute(gmm_lse_kernel, cudaFuncAttributeMaxDynamicSharedMemorySize, SMEM_TOTAL);
    gmm_lse_kernel<<<NCTAS, THREADS, SMEM_TOTAL>>>(x, mu, prec, out);
}

// round 9
// speedup vs baseline: 1.2135x; 1.0197x over previous
#include <cuda_runtime.h>
#include <cuda_bf16.h>
#include <cuda_fp16.h>
#include <cstdint>

// Problem constants
#define NROWS 131072
#define KMU   256
#define DDIM  128
#define MT    128                 // rows per CTA tile
#define NTILES (NROWS / MT)       // 1024
#define NCTAS  296                // 2 per SM
#define THREADS 256

// padded smem row: 128 bf16 + 8 pad = 136 elems = 272 bytes (conflict-free ldmatrix)
#define RSTRIDE 272
#define BUFSZ   (MT * RSTRIDE)    // 34816 per x buffer

// dynamic smem byte offsets
// [0 .. 69632): prologue = W tile (256 x 272); afterwards = 2 x-tile buffers
#define SBUF  0
#define SADJ  69632                   // 256 floats
#define SMP   70656                   // 128 x 9 float2 (padded, conflict-free)
#define SRED  79872                   // 8 floats
#define SMEM_TOTAL 79936

#define L2E 1.4426950408889634f
#define LN2 0.69314718055994531f

__device__ float g_partials[NCTAS];
__device__ unsigned int g_count = 0;

__device__ __forceinline__ uint32_t smem_u32(const void* p) {
    uint32_t a;
    asm("{ .reg .u64 t; cvta.to.shared.u64 t, %1; cvt.u32.u64 %0, t; }" : "=r"(a) : "l"(p));
    return a;
}

__device__ __forceinline__ void ldm_x4(uint32_t addr, uint32_t& r0, uint32_t& r1,
                                       uint32_t& r2, uint32_t& r3) {
    asm volatile("ldmatrix.sync.aligned.m8n8.x4.shared.b16 {%0,%1,%2,%3}, [%4];"
                 : "=r"(r0), "=r"(r1), "=r"(r2), "=r"(r3) : "r"(addr));
}

__device__ __forceinline__ void mma16816(float* d, const uint32_t* a, const uint32_t* b) {
    asm volatile(
        "mma.sync.aligned.m16n8k16.row.col.f32.bf16.bf16.f32 "
        "{%0,%1,%2,%3}, {%4,%5,%6,%7}, {%8,%9}, {%0,%1,%2,%3};"
        : "+f"(d[0]), "+f"(d[1]), "+f"(d[2]), "+f"(d[3])
        : "r"(a[0]), "r"(a[1]), "r"(a[2]), "r"(a[3]), "r"(b[0]), "r"(b[1]));
}

__device__ __forceinline__ float ex2f(float x) {
    float y; asm("ex2.approx.ftz.f32 %0, %1;" : "=f"(y) : "f"(x)); return y;
}
__device__ __forceinline__ float lg2f(float x) {
    float y; asm("lg2.approx.ftz.f32 %0, %1;" : "=f"(y) : "f"(x)); return y;
}

__device__ __forceinline__ __half2 shfl_xor_h2(__half2 v, int o) {
    uint32_t u = *(uint32_t*)&v;
    u = __shfl_xor_sync(0xFFFFFFFFu, u, o);
    return *(__half2*)&u;
}

__global__ void __launch_bounds__(THREADS, 2)
gmm_lse_kernel(const float* __restrict__ x, const float* __restrict__ mu,
               const float* __restrict__ prec, float* __restrict__ out) {
    extern __shared__ char smem[];
    const uint32_t sb = smem_u32(smem);
    const int tid = threadIdx.x;
    const int w = tid >> 5;
    const int l = tid & 31;
    const int m = l >> 3, r = l & 7;

    float*  adj_s = (float*)(smem + SADJ);
    float2* mp_s  = (float2*)(smem + SMP);
    float*  red_s = (float*)(smem + SRED);
    __shared__ unsigned int last_flag;

    // per-lane precision slice (cols 4l..4l+3)
    const float4 pc = ((const float4*)prec)[l];

    // ---- prologue: stage W = prec*mu as bf16 into [0,69632), adj[k] ----
    {
        const float4* mr = (const float4*)(mu + (long)(w * 32) * DDIM);
        #pragma unroll 4
        for (int i = 0; i < 32; i++) {
            const int krow = w * 32 + i;
            float4 f = mr[i * 32 + l];
            float wx = pc.x * f.x, wy = pc.y * f.y, wz = pc.z * f.z, ww = pc.w * f.w;
            float s = wx * f.x;
            s = fmaf(wy, f.y, s);
            s = fmaf(wz, f.z, s);
            s = fmaf(ww, f.w, s);
            #pragma unroll
            for (int o = 16; o; o >>= 1) s += __shfl_xor_sync(0xFFFFFFFFu, s, o);
            __nv_bfloat162 lo = __floats2bfloat162_rn(wx, wy);
            __nv_bfloat162 hi = __floats2bfloat162_rn(wz, ww);
            uint2 v;
            v.x = *(uint32_t*)&lo;
            v.y = *(uint32_t*)&hi;
            *(uint2*)(smem + SBUF + krow * RSTRIDE + l * 8) = v;
            if (l == 0) adj_s[krow] = -0.5f * s * L2E;
        }
    }
    __syncthreads();

    // ---- load register-resident B fragments: warp w owns clusters w*32..w*32+31 ----
    uint32_t B[8][2][4];
    #pragma unroll
    for (int ks = 0; ks < 8; ks++) {
        #pragma unroll
        for (int tp = 0; tp < 2; tp++) {
            uint32_t addr = sb + SBUF
                + (w * 32 + tp * 16 + ((m >> 1) << 3) + r) * RSTRIDE
                + ((ks << 4) + ((m & 1) << 3)) * 2;
            ldm_x4(addr, B[ks][tp][0], B[ks][tp][1], B[ks][tp][2], B[ks][tp][3]);
        }
    }
    // adj values for this lane's 8 columns as half2 (constant across tiles)
    __half2 av_h[4];
    #pragma unroll
    for (int t = 0; t < 4; t++) {
        const int col = w * 32 + 8 * t + 2 * (l & 3);
        av_h[t] = __floats2half2_rn(adj_s[col], adj_s[col + 1]);
    }
    const __half2 l2e2 = __floats2half2_rn(L2E, L2E);
    __syncthreads();   // done reading W region; becomes x double-buffer

    float acc_thr = 0.f;
    float xsq_acc = 0.f;

    // ---- stage first tile into buf0 ----
    {
        const int tile0 = blockIdx.x;
        const float4* xr = (const float4*)(x + (long)(tile0 * MT + w * 16) * DDIM);
        #pragma unroll 8
        for (int i = 0; i < 16; i++) {
            float4 f = xr[i * 32 + l];
            xsq_acc = fmaf(pc.x * f.x, f.x, xsq_acc);
            xsq_acc = fmaf(pc.y * f.y, f.y, xsq_acc);
            xsq_acc = fmaf(pc.z * f.z, f.z, xsq_acc);
            xsq_acc = fmaf(pc.w * f.w, f.w, xsq_acc);
            __nv_bfloat162 lo = __floats2bfloat162_rn(f.x, f.y);
            __nv_bfloat162 hi = __floats2bfloat162_rn(f.z, f.w);
            uint2 v;
            v.x = *(uint32_t*)&lo;
            v.y = *(uint32_t*)&hi;
            *(uint2*)(smem + SBUF + (w * 16 + i) * RSTRIDE + l * 8) = v;
        }
    }
    __syncthreads();

    int par = 0;
    for (int tile = blockIdx.x; tile < NTILES; tile += gridDim.x, par ^= 1) {
        const uint32_t cur = sb + SBUF + par * BUFSZ;

        // ---- stage NEXT tile into the other buffer (LDGs issue before compute) ----
        const int nxt = tile + gridDim.x;
        if (nxt < NTILES) {
            const float4* xr = (const float4*)(x + (long)(nxt * MT + w * 16) * DDIM);
            #pragma unroll 8
            for (int i = 0; i < 16; i++) {
                float4 f = xr[i * 32 + l];
                xsq_acc = fmaf(pc.x * f.x, f.x, xsq_acc);
                xsq_acc = fmaf(pc.y * f.y, f.y, xsq_acc);
                xsq_acc = fmaf(pc.z * f.z, f.z, xsq_acc);
                xsq_acc = fmaf(pc.w * f.w, f.w, xsq_acc);
                __nv_bfloat162 lo = __floats2bfloat162_rn(f.x, f.y);
                __nv_bfloat162 hi = __floats2bfloat162_rn(f.z, f.w);
                uint2 v;
                v.x = *(uint32_t*)&lo;
                v.y = *(uint32_t*)&hi;
                *(uint2*)(smem + SBUF + (par ^ 1) * BUFSZ + (w * 16 + i) * RSTRIDE + l * 8) = v;
            }
        }

        // ---- compute: warp w = all 128 rows x its 32 clusters ----
        #pragma unroll 1
        for (int mt = 0; mt < 8; mt++) {
            float acc[4][4] = {};
            uint32_t a0[4], a1[4];
            {   // prefetch ks=0
                uint32_t addr = cur + (mt * 16 + ((m & 1) << 3) + r) * RSTRIDE
                              + (((m >> 1) << 3)) * 2;
                ldm_x4(addr, a0[0], a0[1], a0[2], a0[3]);
            }
            #pragma unroll
            for (int ks = 0; ks < 8; ks++) {
                uint32_t* ac = (ks & 1) ? a1 : a0;
                uint32_t* an = (ks & 1) ? a0 : a1;
                if (ks < 7) {
                    uint32_t addr = cur + (mt * 16 + ((m & 1) << 3) + r) * RSTRIDE
                                  + (((ks + 1) << 4) + ((m >> 1) << 3)) * 2;
                    ldm_x4(addr, an[0], an[1], an[2], an[3]);
                }
                #pragma unroll
                for (int t = 0; t < 4; t++)
                    mma16816(acc[t], ac, &B[ks][t >> 1][(t & 1) * 2]);
            }
            // ---- half2 epilogue: per-row (max,sum) over this warp's 32 cols ----
            #pragma unroll
            for (int sub = 0; sub < 2; sub++) {
                __half2 vh[4];
                #pragma unroll
                for (int t = 0; t < 4; t++)
                    vh[t] = __hfma2(__floats2half2_rn(acc[t][sub * 2], acc[t][sub * 2 + 1]),
                                    l2e2, av_h[t]);
                __half2 mx = __hmax2(__hmax2(vh[0], vh[1]), __hmax2(vh[2], vh[3]));
                mx = __hmax2(mx, __lowhigh2highlow(mx));
                mx = __hmax2(mx, shfl_xor_h2(mx, 1));
                mx = __hmax2(mx, shfl_xor_h2(mx, 2));     // quad-common max, both halves
                __half2 e0 = h2exp2(__hsub2(vh[0], mx));
                __half2 e1 = h2exp2(__hsub2(vh[1], mx));
                __half2 e2 = h2exp2(__hsub2(vh[2], mx));
                __half2 e3 = h2exp2(__hsub2(vh[3], mx));
                e0 = __hadd2(__hadd2(e0, e1), __hadd2(e2, e3));
                e0 = __hadd2(e0, __lowhigh2highlow(e0));  // lane total (both halves)
                e0 = __hadd2(e0, shfl_xor_h2(e0, 1));
                e0 = __hadd2(e0, shfl_xor_h2(e0, 2));     // 32-col sum
                if ((l & 3) == 0) {
                    const int row = mt * 16 + sub * 8 + (l >> 2);
                    mp_s[row * 9 + w] = make_float2(__low2float(mx), __low2float(e0));
                }
            }
        }
        __syncthreads();

        // ---- exact 8-way cross-warp merge; threads 0..127 own one row each ----
        if (tid < MT) {
            float2 p[8];
            #pragma unroll
            for (int j = 0; j < 8; j++) p[j] = mp_s[tid * 9 + j];
            float m8 = p[0].x;
            #pragma unroll
            for (int j = 1; j < 8; j++) m8 = fmaxf(m8, p[j].x);
            float s8 = 0.f;
            #pragma unroll
            for (int j = 0; j < 8; j++) s8 += p[j].y * ex2f(p[j].x - m8);
            acc_thr += LN2 * (m8 + lg2f(s8));
        }
        __syncthreads();
    }

    // fold thread-local xsq (additive pass-through of logsumexp)
    acc_thr -= 0.5f * xsq_acc;

    // ---- deterministic block reduction ----
    float a = acc_thr;
    #pragma unroll
    for (int o = 16; o; o >>= 1) a += __shfl_xor_sync(0xFFFFFFFFu, a, o);
    if (l == 0) red_s[w] = a;
    __syncthreads();
    if (tid == 0) {
        float t = 0.f;
        #pragma unroll
        for (int i = 0; i < 8; i++) t += red_s[i];
        g_partials[blockIdx.x] = t;
        __threadfence();
        unsigned int c = atomicAdd(&g_count, 1u);
        last_flag = (c == (unsigned)(gridDim.x - 1)) ? 1u : 0u;
    }
    __syncthreads();

    // ---- last CTA: deterministic final reduction (fixed lane->index map) ----
    if (last_flag && w == 0) {
        float s = 0.f;
        #pragma unroll
        for (int i = l; i < NCTAS; i += 32) s += __ldcg(&g_partials[i]);
        #pragma unroll
        for (int o = 16; o; o >>= 1) s += __shfl_xor_sync(0xFFFFFFFFu, s, o);
        if (l == 0) {
            out[0] = -s;
            g_count = 0;          // reset for next graph replay
            __threadfence();
        }
    }
}

extern "C" void kernel_launch(void* const* d_in, const int* in_sizes, int n_in,
                              void* d_out, int out_size) {
    const float* x    = (const float*)d_in[0];
    const float* mu   = (const float*)d_in[1];
    const float* prec = (const float*)d_in[2];
    float* out = (float*)d_out;

    cudaFuncSetAttribute(gmm_lse_kernel, cudaFuncAttributeMaxDynamicSharedMemorySize, SMEM_TOTAL);
    gmm_lse_kernel<<<NCTAS, THREADS, SMEM_TOTAL>>>(x, mu, prec, out);
}